// round 1
// baseline (speedup 1.0000x reference)
#include <cuda_runtime.h>
#include <cstdint>
#include <math.h>

// Problem constants
#define BB 32
#define NN 1024
#define DD 1152
#define RR 4
#define MM 256   // NN/RR

// GEMM tile config
#define BM 128
#define BN 128
#define BK 16
#define KST 20   // padded smem row stride (floats): 20*4=80B, 16B aligned, conflict-free reads

// ---------------- scratch (device globals; no allocation allowed) ----------------
__device__ float g_xm [(size_t)BB * MM * DD];   // merged x            [32,256,1152]
__device__ float g_Q  [(size_t)BB * NN * DD];   // Q                   [32,1024,1152]
__device__ float g_Km [(size_t)BB * MM * DD];   // K merged            [32,256,1152]
__device__ float g_VmT[(size_t)BB * DD * MM];   // V merged, transposed[32,1152,256]
__device__ float g_S  [(size_t)BB * NN * MM];   // scores/probs        [32,1024,256]
__device__ float g_AO [(size_t)BB * NN * DD];   // attention output    [32,1024,1152]

// ---------------- helpers ----------------
__device__ __forceinline__ uint32_t f2tf32(float f) {
    uint32_t u;
    asm("cvt.rna.tf32.f32 %0, %1;" : "=r"(u) : "f"(f));
    return u;
}

__device__ __forceinline__ void cp_async16(uint32_t smem, const float* gmem) {
    asm volatile("cp.async.cg.shared.global [%0], [%1], 16;\n" :: "r"(smem), "l"(gmem));
}
__device__ __forceinline__ void cp_commit() {
    asm volatile("cp.async.commit_group;\n" ::: "memory");
}

__device__ __forceinline__ void mma_tf32(float c[4], const uint32_t a[4], const uint32_t b[2]) {
    asm volatile(
        "mma.sync.aligned.m16n8k8.row.col.f32.tf32.tf32.f32 "
        "{%0,%1,%2,%3}, {%4,%5,%6,%7}, {%8,%9}, {%0,%1,%2,%3};"
        : "+f"(c[0]), "+f"(c[1]), "+f"(c[2]), "+f"(c[3])
        : "r"(a[0]), "r"(a[1]), "r"(a[2]), "r"(a[3]), "r"(b[0]), "r"(b[1]));
}

// ---------------- kernel 1: window-mean merge  x[B,N,D] -> xm[B,M,D] ----------------
__global__ __launch_bounds__(256) void merge_mean(const float* __restrict__ x,
                                                  float* __restrict__ xm) {
    const int D4 = DD / 4;  // 288
    size_t idx = (size_t)blockIdx.x * blockDim.x + threadIdx.x;
    size_t tot = (size_t)BB * MM * D4;
    if (idx >= tot) return;
    int d4 = (int)(idx % D4);
    size_t orow = idx / D4;           // b*256 + m
    int b = (int)(orow >> 8);
    int m = (int)(orow & 255);
    const float4* base = (const float4*)x + ((size_t)b * NN + (size_t)m * RR) * D4 + d4;
    float4 a0 = base[0];
    float4 a1 = base[D4];
    float4 a2 = base[2 * D4];
    float4 a3 = base[3 * D4];
    float4 o;
    o.x = 0.25f * (a0.x + a1.x + a2.x + a3.x);
    o.y = 0.25f * (a0.y + a1.y + a2.y + a3.y);
    o.z = 0.25f * (a0.z + a1.z + a2.z + a3.z);
    o.w = 0.25f * (a0.w + a1.w + a2.w + a3.w);
    ((float4*)xm)[idx] = o;
}

// ---------------- kernel 2: generic batched tf32 GEMM ----------------
// C[b][i][j] = alpha * sum_k A[b][i][k] * Bm[b][j][k]  (+ bias[j] if bias)
// If transC: C[b] laid out [Ncols][Mrows] (element at j*Mrows + i).
// Requires: Mrows%128==0, Ncols%128==0, K%16==0, 16B-aligned pointers.
__global__ __launch_bounds__(256) void gemm_tf32(
    const float* __restrict__ A, const float* __restrict__ Bm,
    const float* __restrict__ bias, float* __restrict__ C,
    int Mrows, int Ncols, int K,
    long long sA, long long sB, long long sC,
    float alpha, int transC)
{
    __shared__ float As[2][BM * KST];
    __shared__ float Bs[2][BN * KST];

    const int bz = blockIdx.z;
    const float* Ab = A + (size_t)bz * sA;
    const float* Bb = Bm + (size_t)bz * sB;
    float* Cb = C + (size_t)bz * sC;

    const int tid = threadIdx.x;
    const int warp = tid >> 5, lane = tid & 31;
    const int wm = warp & 1;        // 0..1 (64 rows each)
    const int wn = warp >> 1;       // 0..3 (32 cols each)
    const int rr = lane >> 2;       // group id 0..7
    const int cc = lane & 3;        // thread-in-group

    const int rowA0 = blockIdx.x * BM;
    const int rowB0 = blockIdx.y * BN;

    float acc[4][4][4];
#pragma unroll
    for (int i = 0; i < 4; i++)
#pragma unroll
        for (int j = 0; j < 4; j++)
#pragma unroll
            for (int k = 0; k < 4; k++) acc[i][j][k] = 0.0f;

    const int KT = K / BK;

    // per-thread load assignment (512 16B-chunks per operand tile, 256 threads -> 2 each)
    auto load_tile = [&](int buf, int kt) {
#pragma unroll
        for (int i = 0; i < 2; i++) {
            int c = tid + i * 256;
            int r = c >> 2;
            int kv = (c & 3) * 4;
            const float* gA = Ab + (size_t)(rowA0 + r) * K + kt * BK + kv;
            uint32_t sa = (uint32_t)__cvta_generic_to_shared(&As[buf][r * KST + kv]);
            cp_async16(sa, gA);
            const float* gB = Bb + (size_t)(rowB0 + r) * K + kt * BK + kv;
            uint32_t sb = (uint32_t)__cvta_generic_to_shared(&Bs[buf][r * KST + kv]);
            cp_async16(sb, gB);
        }
        cp_commit();
    };

    load_tile(0, 0);

    for (int kt = 0; kt < KT; kt++) {
        const int buf = kt & 1;
        if (kt + 1 < KT) {
            load_tile(buf ^ 1, kt + 1);
            asm volatile("cp.async.wait_group 1;\n" ::: "memory");
        } else {
            asm volatile("cp.async.wait_group 0;\n" ::: "memory");
        }
        __syncthreads();

        const float* As_ = &As[buf][0];
        const float* Bs_ = &Bs[buf][0];
#pragma unroll
        for (int ks = 0; ks < 2; ks++) {
            const int kb = ks * 8;
            uint32_t af[4][4], bf[4][2];
#pragma unroll
            for (int mi = 0; mi < 4; mi++) {
                int base = (wm * 64 + mi * 16 + rr) * KST + kb + cc;
                af[mi][0] = f2tf32(As_[base]);
                af[mi][1] = f2tf32(As_[base + 8 * KST]);
                af[mi][2] = f2tf32(As_[base + 4]);
                af[mi][3] = f2tf32(As_[base + 8 * KST + 4]);
            }
#pragma unroll
            for (int ni = 0; ni < 4; ni++) {
                int base = (wn * 32 + ni * 8 + rr) * KST + kb + cc;
                bf[ni][0] = f2tf32(Bs_[base]);
                bf[ni][1] = f2tf32(Bs_[base + 4]);
            }
#pragma unroll
            for (int mi = 0; mi < 4; mi++)
#pragma unroll
                for (int ni = 0; ni < 4; ni++)
                    mma_tf32(acc[mi][ni], af[mi], bf[ni]);
        }
        __syncthreads();
    }

    // epilogue
#pragma unroll
    for (int mi = 0; mi < 4; mi++) {
#pragma unroll
        for (int ni = 0; ni < 4; ni++) {
            int gr = rowA0 + wm * 64 + mi * 16 + rr;
            int gc = rowB0 + wn * 32 + ni * 8 + 2 * cc;
            float b0v = 0.0f, b1v = 0.0f;
            if (bias) { b0v = bias[gc]; b1v = bias[gc + 1]; }
            float v00 = acc[mi][ni][0] * alpha + b0v;
            float v01 = acc[mi][ni][1] * alpha + b1v;
            float v10 = acc[mi][ni][2] * alpha + b0v;
            float v11 = acc[mi][ni][3] * alpha + b1v;
            if (!transC) {
                float2* o0 = (float2*)(Cb + (size_t)gr * Ncols + gc);
                *o0 = make_float2(v00, v01);
                float2* o1 = (float2*)(Cb + (size_t)(gr + 8) * Ncols + gc);
                *o1 = make_float2(v10, v11);
            } else {
                Cb[(size_t)gc * Mrows + gr]           = v00;
                Cb[(size_t)(gc + 1) * Mrows + gr]     = v01;
                Cb[(size_t)gc * Mrows + gr + 8]       = v10;
                Cb[(size_t)(gc + 1) * Mrows + gr + 8] = v11;
            }
        }
    }
}

// ---------------- kernel 3: softmax over last dim (256), in place ----------------
__global__ __launch_bounds__(256) void softmax256(float* __restrict__ S) {
    int row = blockIdx.x * 8 + (threadIdx.x >> 5);
    int lane = threadIdx.x & 31;
    float4* p = (float4*)(S + (size_t)row * MM);
    float4 v0 = p[lane];
    float4 v1 = p[lane + 32];

    float m = fmaxf(fmaxf(fmaxf(v0.x, v0.y), fmaxf(v0.z, v0.w)),
                    fmaxf(fmaxf(v1.x, v1.y), fmaxf(v1.z, v1.w)));
#pragma unroll
    for (int off = 16; off > 0; off >>= 1)
        m = fmaxf(m, __shfl_xor_sync(0xFFFFFFFFu, m, off));

    v0.x = __expf(v0.x - m); v0.y = __expf(v0.y - m);
    v0.z = __expf(v0.z - m); v0.w = __expf(v0.w - m);
    v1.x = __expf(v1.x - m); v1.y = __expf(v1.y - m);
    v1.z = __expf(v1.z - m); v1.w = __expf(v1.w - m);

    float s = v0.x + v0.y + v0.z + v0.w + v1.x + v1.y + v1.z + v1.w;
#pragma unroll
    for (int off = 16; off > 0; off >>= 1)
        s += __shfl_xor_sync(0xFFFFFFFFu, s, off);

    float inv = 1.0f / s;
    v0.x *= inv; v0.y *= inv; v0.z *= inv; v0.w *= inv;
    v1.x *= inv; v1.y *= inv; v1.z *= inv; v1.w *= inv;
    p[lane] = v0;
    p[lane + 32] = v1;
}

// ---------------- launch ----------------
extern "C" void kernel_launch(void* const* d_in, const int* in_sizes, int n_in,
                              void* d_out, int out_size) {
    static float *p_xm = nullptr, *p_Q, *p_Km, *p_VmT, *p_S, *p_AO;
    if (!p_xm) {
        cudaGetSymbolAddress((void**)&p_xm,  g_xm);
        cudaGetSymbolAddress((void**)&p_Q,   g_Q);
        cudaGetSymbolAddress((void**)&p_Km,  g_Km);
        cudaGetSymbolAddress((void**)&p_VmT, g_VmT);
        cudaGetSymbolAddress((void**)&p_S,   g_S);
        cudaGetSymbolAddress((void**)&p_AO,  g_AO);
    }

    const float* x  = (const float*)d_in[0];
    const float* Wq = (const float*)d_in[1];
    const float* bq = (const float*)d_in[2];
    const float* Wk = (const float*)d_in[3];
    const float* bk = (const float*)d_in[4];
    const float* Wv = (const float*)d_in[5];
    const float* bv = (const float*)d_in[6];
    const float* Wo = (const float*)d_in[7];
    const float* bo = (const float*)d_in[8];
    float* out = (float*)d_out;

    const float scale = 1.0f / sqrtf((float)DD);
    dim3 blk(256);

    // 0. x_m = window mean of x
    merge_mean<<<(BB * MM * (DD / 4)) / 256, blk>>>(x, p_xm);

    // 1. Q = x @ Wq^T + bq      [32768, 1152]
    gemm_tf32<<<dim3((BB * NN) / BM, DD / BN, 1), blk>>>(
        x, Wq, bq, p_Q, BB * NN, DD, DD, 0, 0, 0, 1.0f, 0);

    // 2. K_m = x_m @ Wk^T + bk  [8192, 1152]
    gemm_tf32<<<dim3((BB * MM) / BM, DD / BN, 1), blk>>>(
        p_xm, Wk, bk, p_Km, BB * MM, DD, DD, 0, 0, 0, 1.0f, 0);

    // 3. V_mT = (x_m @ Wv^T + bv)^T per batch  -> [32][1152][256]
    gemm_tf32<<<dim3(MM / BM, DD / BN, BB), blk>>>(
        p_xm, Wv, bv, p_VmT, MM, DD, DD,
        (long long)MM * DD, 0, (long long)DD * MM, 1.0f, 1);

    // 4. S = scale * Q @ K_m^T  (log(npt) bias dropped: softmax-invariant)
    gemm_tf32<<<dim3(NN / BM, MM / BN, BB), blk>>>(
        p_Q, p_Km, nullptr, p_S, NN, MM, DD,
        (long long)NN * DD, (long long)MM * DD, (long long)NN * MM, scale, 0);

    // 5. softmax rows of S
    softmax256<<<(BB * NN) / 8, blk>>>(p_S);

    // 6. AO = P @ V_m   (B operand = V_mT, K-major)
    gemm_tf32<<<dim3(NN / BM, DD / BN, BB), blk>>>(
        p_S, p_VmT, nullptr, p_AO, NN, DD, MM,
        (long long)NN * MM, (long long)DD * MM, (long long)NN * DD, 1.0f, 0);

    // 7. out = AO @ Wo^T + bo
    gemm_tf32<<<dim3((BB * NN) / BM, DD / BN, 1), blk>>>(
        p_AO, Wo, bo, out, BB * NN, DD, DD, 0, 0, 0, 1.0f, 0);
}